// round 1
// baseline (speedup 1.0000x reference)
#include <cuda_runtime.h>
#include <cstdint>
#include <cstddef>

// Problem constants
#define BATCH 2
#define SEQ   2048
#define DMODEL 1024
#define NHEAD 16
#define DHEAD 64
#define BH    (BATCH*NHEAD)

// Scratch (device globals: allocation-free rule)
__device__ float g_Q[(size_t)BH * SEQ * DHEAD];        // 16 MB
__device__ float g_K[(size_t)BH * SEQ * DHEAD];        // 16 MB
__device__ float g_V[(size_t)BH * SEQ * DHEAD];        // 16 MB
__device__ float g_P[(size_t)BH * SEQ * SEQ];          // 512 MB (only causal half touched)
__device__ float g_den[(size_t)BH * SEQ];              // holds 1/colsum
__device__ float g_Ocat[(size_t)BATCH * SEQ * DMODEL]; // 16 MB

// ---------------------------------------------------------------------------
// Per-head projection: Out[b,h,q,e] = sum_d X[b,q,d] * W[h,d,e]
// which: 0 -> g_Q, 1 -> g_K, 2 -> g_V
// ---------------------------------------------------------------------------
__global__ __launch_bounds__(256) void proj_kernel(const float* __restrict__ X,
                                                   const float* __restrict__ W,
                                                   int which) {
    int qt = blockIdx.x;   // 0..31 (64-row tile)
    int h  = blockIdx.y;   // 0..15
    int b  = blockIdx.z;   // 0..1

    __shared__ float Xs[64][16];
    __shared__ float Ws[16][64];

    const float* Xb = X + (size_t)b * SEQ * DMODEL + (size_t)qt * 64 * DMODEL;
    const float* Wh = W + (size_t)h * DMODEL * DHEAD;

    int t  = threadIdx.x;
    int r0 = (t >> 4) << 2;   // output row base (0..60)
    int c0 = (t & 15) << 2;   // output col base (0..60)

    float acc[4][4] = {};

    int lr = t >> 2;            // Xs load row 0..63
    int lc = (t & 3) << 2;      // Xs load col 0,4,8,12
    int wr = t >> 4;            // Ws load row 0..15
    int wc = (t & 15) << 2;     // Ws load col 0..60

    for (int kk = 0; kk < DMODEL; kk += 16) {
        *(float4*)&Xs[lr][lc] = *(const float4*)&Xb[(size_t)lr * DMODEL + kk + lc];
        *(float4*)&Ws[wr][wc] = *(const float4*)&Wh[(size_t)(kk + wr) * DHEAD + wc];
        __syncthreads();
#pragma unroll
        for (int c = 0; c < 16; c++) {
            float b0 = Ws[c][c0], b1 = Ws[c][c0 + 1], b2 = Ws[c][c0 + 2], b3 = Ws[c][c0 + 3];
#pragma unroll
            for (int i = 0; i < 4; i++) {
                float a = Xs[r0 + i][c];
                acc[i][0] += a * b0; acc[i][1] += a * b1;
                acc[i][2] += a * b2; acc[i][3] += a * b3;
            }
        }
        __syncthreads();
    }

    float* Outp = (which == 0) ? g_Q : (which == 1) ? g_K : g_V;
    float* Ob = Outp + ((size_t)(b * NHEAD + h) * SEQ + (size_t)qt * 64) * DHEAD;
#pragma unroll
    for (int i = 0; i < 4; i++) {
        float4 v = make_float4(acc[i][0], acc[i][1], acc[i][2], acc[i][3]);
        *(float4*)&Ob[(size_t)(r0 + i) * DHEAD + c0] = v;
    }
}

// ---------------------------------------------------------------------------
// Scores: P[bh,q,k] = exp((Q.K + (k-q)) * 1/sqrt(S)) for k<=q else 0
// Triangular: blocks with kt>qt do nothing (P stays zero-initialized there).
// ---------------------------------------------------------------------------
__global__ __launch_bounds__(256) void scores_kernel() {
    int kt = blockIdx.x, qt = blockIdx.y, bh = blockIdx.z;
    if (kt > qt) return;

    __shared__ float Qs[64][64];
    __shared__ float Kst[64][68];  // transposed K tile, padded (aligned float4 rows)

    int t = threadIdx.x;
    const float* Qb = g_Q + ((size_t)bh * SEQ + (size_t)qt * 64) * DHEAD;
    const float* Kb = g_K + ((size_t)bh * SEQ + (size_t)kt * 64) * DHEAD;

#pragma unroll
    for (int u = 0; u < 4; u++) {
        int f4 = t + u * 256;
        int row = f4 >> 4, col = (f4 & 15) << 2;
        *(float4*)&Qs[row][col] = *(const float4*)&Qb[(size_t)row * DHEAD + col];
        float4 v = *(const float4*)&Kb[(size_t)row * DHEAD + col];
        Kst[col][row] = v.x; Kst[col + 1][row] = v.y;
        Kst[col + 2][row] = v.z; Kst[col + 3][row] = v.w;
    }
    __syncthreads();

    int r0 = (t >> 4) << 2;
    int c0 = (t & 15) << 2;
    float acc[4][4] = {};

#pragma unroll
    for (int e = 0; e < 64; e++) {
        float4 bv = *(float4*)&Kst[e][c0];
#pragma unroll
        for (int i = 0; i < 4; i++) {
            float a = Qs[r0 + i][e];
            acc[i][0] += a * bv.x; acc[i][1] += a * bv.y;
            acc[i][2] += a * bv.z; acc[i][3] += a * bv.w;
        }
    }

    const float sc = 0.022097086912079608f; // 1/sqrt(2048)
    int q0 = qt * 64, k0 = kt * 64;
    float* Pb = g_P + ((size_t)bh * SEQ + q0) * SEQ + k0;
#pragma unroll
    for (int i = 0; i < 4; i++) {
        int q = q0 + r0 + i;
#pragma unroll
        for (int j = 0; j < 4; j++) {
            int k = k0 + c0 + j;
            float v = 0.0f;
            if (k <= q) v = expf((acc[i][j] + (float)(k - q)) * sc);
            acc[i][j] = v;
        }
        float4 v4 = make_float4(acc[i][0], acc[i][1], acc[i][2], acc[i][3]);
        *(float4*)&Pb[(size_t)(r0 + i) * SEQ + c0] = v4;
    }
}

// ---------------------------------------------------------------------------
// Column sums of P over q (deterministic, no atomics) -> store reciprocal.
// Block = (kt, bh): 64 columns; only rows q >= kt*64 can be nonzero.
// ---------------------------------------------------------------------------
__global__ __launch_bounds__(256) void colsum_kernel() {
    int kt = blockIdx.x, bh = blockIdx.y;
    int t = threadIdx.x;
    int col = t & 63, qo = t >> 6;  // 4 rows in flight

    const float* Pb = g_P + (size_t)bh * SEQ * SEQ + (size_t)kt * 64;
    float s = 0.0f;
    for (int q = kt * 64 + qo; q < SEQ; q += 4)
        s += Pb[(size_t)q * SEQ + col];

    __shared__ float red[256];
    red[t] = s;
    __syncthreads();
    if (t < 64) {
        float tot = red[t] + red[t + 64] + red[t + 128] + red[t + 192];
        g_den[(size_t)bh * SEQ + kt * 64 + t] = 1.0f / tot;
    }
}

// ---------------------------------------------------------------------------
// PV GEMM: Ocat[b, q, h*64+e] = sum_k P[q,k] * invden[k] * V[k,e]
// invden folded into the V tile load.
// ---------------------------------------------------------------------------
__global__ __launch_bounds__(256) void pv_kernel() {
    int qt = blockIdx.x, bh = blockIdx.y;
    int b = bh >> 4, h = bh & 15;

    __shared__ float Ps[64][64];
    __shared__ float Vs[64][64];

    int t = threadIdx.x;
    int r0 = (t >> 4) << 2;
    int c0 = (t & 15) << 2;
    float acc[4][4] = {};

    const float* Prow = g_P + ((size_t)bh * SEQ + (size_t)qt * 64) * SEQ;
    const float* Vb = g_V + (size_t)bh * SEQ * DHEAD;
    const float* inv = g_den + (size_t)bh * SEQ;

    for (int kt = 0; kt <= qt; kt++) {
        int kbase = kt * 64;
#pragma unroll
        for (int u = 0; u < 4; u++) {
            int f4 = t + u * 256;
            int row = f4 >> 4, col = (f4 & 15) << 2;
            *(float4*)&Ps[row][col] =
                *(const float4*)&Prow[(size_t)row * SEQ + kbase + col];
            float iv = inv[kbase + row];
            float4 v = *(const float4*)&Vb[(size_t)(kbase + row) * DHEAD + col];
            v.x *= iv; v.y *= iv; v.z *= iv; v.w *= iv;
            *(float4*)&Vs[row][col] = v;
        }
        __syncthreads();
#pragma unroll
        for (int kk = 0; kk < 64; kk++) {
            float4 bv = *(float4*)&Vs[kk][c0];
#pragma unroll
            for (int i = 0; i < 4; i++) {
                float a = Ps[r0 + i][kk];
                acc[i][0] += a * bv.x; acc[i][1] += a * bv.y;
                acc[i][2] += a * bv.z; acc[i][3] += a * bv.w;
            }
        }
        __syncthreads();
    }

    float* Ob = g_Ocat + ((size_t)b * SEQ + (size_t)qt * 64) * DMODEL + (size_t)h * DHEAD;
#pragma unroll
    for (int i = 0; i < 4; i++) {
        float4 v = make_float4(acc[i][0], acc[i][1], acc[i][2], acc[i][3]);
        *(float4*)&Ob[(size_t)(r0 + i) * DMODEL + c0] = v;
    }
}

// ---------------------------------------------------------------------------
// Output projection: Out[r, c] = sum_d Ocat[r, d] * WO[d, c]
// r in [0, B*S), c in [0, 1024)
// ---------------------------------------------------------------------------
__global__ __launch_bounds__(256) void out_kernel(const float* __restrict__ WO,
                                                  float* __restrict__ Out) {
    int rt = blockIdx.x;  // 0..63
    int ct = blockIdx.y;  // 0..15

    __shared__ float Xs[64][16];
    __shared__ float Ws[16][64];

    int t = threadIdx.x;
    int r0 = (t >> 4) << 2;
    int c0 = (t & 15) << 2;
    float acc[4][4] = {};

    int lr = t >> 2, lc = (t & 3) << 2;
    int wr = t >> 4, wc = (t & 15) << 2;

    const float* Xb = g_Ocat + (size_t)rt * 64 * DMODEL;
    const float* Wb = WO + (size_t)ct * 64;

    for (int kk = 0; kk < DMODEL; kk += 16) {
        *(float4*)&Xs[lr][lc] = *(const float4*)&Xb[(size_t)lr * DMODEL + kk + lc];
        *(float4*)&Ws[wr][wc] = *(const float4*)&Wb[(size_t)(kk + wr) * DMODEL + wc];
        __syncthreads();
#pragma unroll
        for (int c = 0; c < 16; c++) {
            float b0 = Ws[c][c0], b1 = Ws[c][c0 + 1], b2 = Ws[c][c0 + 2], b3 = Ws[c][c0 + 3];
#pragma unroll
            for (int i = 0; i < 4; i++) {
                float a = Xs[r0 + i][c];
                acc[i][0] += a * b0; acc[i][1] += a * b1;
                acc[i][2] += a * b2; acc[i][3] += a * b3;
            }
        }
        __syncthreads();
    }

    float* Ob = Out + (size_t)rt * 64 * DMODEL + (size_t)ct * 64;
#pragma unroll
    for (int i = 0; i < 4; i++) {
        float4 v = make_float4(acc[i][0], acc[i][1], acc[i][2], acc[i][3]);
        *(float4*)&Ob[(size_t)(r0 + i) * DMODEL + c0] = v;
    }
}

// ---------------------------------------------------------------------------
// Launch
// Inputs (metadata order): keys, queries, values, WQ, WK, WV, WO, masking
// ---------------------------------------------------------------------------
extern "C" void kernel_launch(void* const* d_in, const int* in_sizes, int n_in,
                              void* d_out, int out_size) {
    const float* keys    = (const float*)d_in[0];
    const float* queries = (const float*)d_in[1];
    const float* values  = (const float*)d_in[2];
    const float* WQ      = (const float*)d_in[3];
    const float* WK      = (const float*)d_in[4];
    const float* WV      = (const float*)d_in[5];
    const float* WO      = (const float*)d_in[6];
    float* out = (float*)d_out;
    (void)in_sizes; (void)n_in; (void)out_size;

    dim3 projGrid(SEQ / 64, NHEAD, BATCH);
    proj_kernel<<<projGrid, 256>>>(queries, WQ, 0);
    proj_kernel<<<projGrid, 256>>>(keys,    WK, 1);
    proj_kernel<<<projGrid, 256>>>(values,  WV, 2);

    dim3 scoreGrid(SEQ / 64, SEQ / 64, BH);
    scores_kernel<<<scoreGrid, 256>>>();

    dim3 csGrid(SEQ / 64, BH);
    colsum_kernel<<<csGrid, 256>>>();

    dim3 pvGrid(SEQ / 64, BH);
    pv_kernel<<<pvGrid, 256>>>();

    dim3 outGrid((BATCH * SEQ) / 64, DMODEL / 64);
    out_kernel<<<outGrid, 256>>>(WO, out);
}

// round 2
// speedup vs baseline: 1.0628x; 1.0628x over previous
#include <cuda_runtime.h>
#include <mma.h>
#include <cstdint>
#include <cstddef>

using namespace nvcuda;

#define BATCH  2
#define SEQ    2048
#define DMODEL 1024
#define NHEAD  16
#define DHEAD  64
#define BH     (BATCH*NHEAD)

// Scratch (device globals: allocation-free rule)
__device__ __align__(16) float g_Q[(size_t)BH * SEQ * DHEAD];        // 16 MB
__device__ __align__(16) float g_K[(size_t)BH * SEQ * DHEAD];        // 16 MB
__device__ __align__(16) float g_V[(size_t)BH * SEQ * DHEAD];        // 16 MB
__device__ __align__(16) float g_den[(size_t)BH * SEQ];              // 1/colsum
__device__ __align__(16) float g_Ocat[(size_t)BATCH * SEQ * DMODEL]; // 16 MB

typedef wmma::fragment<wmma::matrix_a, 16, 16, 8, wmma::precision::tf32, wmma::row_major> FragA;
typedef wmma::fragment<wmma::matrix_b, 16, 16, 8, wmma::precision::tf32, wmma::row_major> FragB;
typedef wmma::fragment<wmma::matrix_b, 16, 16, 8, wmma::precision::tf32, wmma::col_major> FragBt;
typedef wmma::fragment<wmma::accumulator, 16, 16, 8, float> FragC;

template <typename F>
__device__ __forceinline__ void to_tf32(F& f) {
#pragma unroll
    for (int i = 0; i < f.num_elements; i++) f.x[i] = wmma::__float_to_tf32(f.x[i]);
}

#define SCALE 0.022097086912079608f  // 1/sqrt(2048)

// ---------------------------------------------------------------------------
// Fused per-head projections: {Q,K,V}[bh, s, e] = X[b, s, :] @ W[h, :, e]
// blockIdx: x = 128-row tile (16), y = head (16), z = which*2 + b (6)
// ---------------------------------------------------------------------------
__global__ __launch_bounds__(256) void proj_kernel(
    const float* __restrict__ Xq, const float* __restrict__ Xk, const float* __restrict__ Xv,
    const float* __restrict__ WQ, const float* __restrict__ WK, const float* __restrict__ WV) {
    int mt = blockIdx.x, h = blockIdx.y, z = blockIdx.z;
    int which = z >> 1, b = z & 1;
    const float* X = (which == 0) ? Xq : (which == 1) ? Xk : Xv;
    const float* W = (which == 0) ? WQ : (which == 1) ? WK : WV;
    float* Outp    = (which == 0) ? g_Q : (which == 1) ? g_K : g_V;

    __shared__ alignas(16) float Xs[128][40];  // 128x32 tile, pad 8
    __shared__ alignas(16) float Ws[32][72];   // 32x64 tile, pad 8

    int t = threadIdx.x, wid = t >> 5;
    int wm = wid >> 1, wn = wid & 1;  // 4x2 warps -> 128x64

    FragC c[2][2];
#pragma unroll
    for (int i = 0; i < 2; i++)
#pragma unroll
        for (int j = 0; j < 2; j++) wmma::fill_fragment(c[i][j], 0.0f);

    const float* Xb = X + (size_t)b * SEQ * DMODEL + (size_t)mt * 128 * DMODEL;
    const float* Wh = W + (size_t)h * DMODEL * DHEAD;

    for (int kk = 0; kk < DMODEL; kk += 32) {
#pragma unroll
        for (int j = 0; j < 4; j++) {
            int id = t + j * 256;
            int row = id >> 3, col = (id & 7) << 2;
            *(float4*)&Xs[row][col] = *(const float4*)&Xb[(size_t)row * DMODEL + kk + col];
        }
#pragma unroll
        for (int j = 0; j < 2; j++) {
            int id = t + j * 256;
            int row = id >> 4, col = (id & 15) << 2;
            *(float4*)&Ws[row][col] = *(const float4*)&Wh[(size_t)(kk + row) * DHEAD + col];
        }
        __syncthreads();
#pragma unroll
        for (int ks = 0; ks < 32; ks += 8) {
            FragA a[2];
            FragB bf[2];
#pragma unroll
            for (int i = 0; i < 2; i++) {
                wmma::load_matrix_sync(a[i], &Xs[wm * 32 + i * 16][ks], 40);
                to_tf32(a[i]);
            }
#pragma unroll
            for (int j = 0; j < 2; j++) {
                wmma::load_matrix_sync(bf[j], &Ws[ks][wn * 32 + j * 16], 72);
                to_tf32(bf[j]);
            }
#pragma unroll
            for (int i = 0; i < 2; i++)
#pragma unroll
                for (int j = 0; j < 2; j++)
                    wmma::mma_sync(c[i][j], a[i], bf[j], c[i][j]);
        }
        __syncthreads();
    }

    float* Ob = Outp + ((size_t)(b * NHEAD + h) * SEQ + (size_t)mt * 128) * DHEAD;
#pragma unroll
    for (int i = 0; i < 2; i++)
#pragma unroll
        for (int j = 0; j < 2; j++)
            wmma::store_matrix_sync(&Ob[(size_t)(wm * 32 + i * 16) * DHEAD + wn * 32 + j * 16],
                                    c[i][j], DHEAD, wmma::mem_row_major);
}

// ---------------------------------------------------------------------------
// Pass A: column-softmax denominators. g_den[bh,k] = 1 / sum_{q>=k} exp(y[q,k])
// block = (kt: 64 k-cols, bh). Loops over 128-row q tiles, scores via wmma.
// ---------------------------------------------------------------------------
__global__ __launch_bounds__(256) void den_kernel() {
    int kt = blockIdx.x, bh = blockIdx.y;
    extern __shared__ float sm[];
    float* Qs = sm;              // 128*72
    float* Ks = Qs + 128 * 72;   // 64*72
    float* Sb = Ks + 64 * 72;    // 128*72

    int t = threadIdx.x, wid = t >> 5;
    int wm = wid >> 1, wn = wid & 1;

    const float* Qb = g_Q + (size_t)bh * SEQ * DHEAD;
    const float* Kb = g_K + ((size_t)bh * SEQ + (size_t)kt * 64) * DHEAD;

#pragma unroll
    for (int j = 0; j < 4; j++) {
        int id = t + j * 256;
        int row = id >> 4, col = (id & 15) << 2;
        *(float4*)&Ks[row * 72 + col] = *(const float4*)&Kb[(size_t)row * DHEAD + col];
    }

    int col = t & 63;
    int k = kt * 64 + col;
    float part = 0.0f;

    for (int qt = kt >> 1; qt < SEQ / 128; qt++) {
        int q0 = qt * 128;
#pragma unroll
        for (int j = 0; j < 8; j++) {
            int id = t + j * 256;
            int row = id >> 4, c4 = (id & 15) << 2;
            *(float4*)&Qs[row * 72 + c4] = *(const float4*)&Qb[(size_t)(q0 + row) * DHEAD + c4];
        }
        __syncthreads();

        FragC cf[2][2];
#pragma unroll
        for (int i = 0; i < 2; i++)
#pragma unroll
            for (int j = 0; j < 2; j++) wmma::fill_fragment(cf[i][j], 0.0f);

#pragma unroll
        for (int ks = 0; ks < 64; ks += 8) {
            FragA a[2];
            FragBt bf[2];
#pragma unroll
            for (int i = 0; i < 2; i++) {
                wmma::load_matrix_sync(a[i], &Qs[(wm * 32 + i * 16) * 72 + ks], 72);
                to_tf32(a[i]);
            }
#pragma unroll
            for (int j = 0; j < 2; j++) {
                wmma::load_matrix_sync(bf[j], &Ks[(wn * 32 + j * 16) * 72 + ks], 72);
                to_tf32(bf[j]);
            }
#pragma unroll
            for (int i = 0; i < 2; i++)
#pragma unroll
                for (int j = 0; j < 2; j++)
                    wmma::mma_sync(cf[i][j], a[i], bf[j], cf[i][j]);
        }
#pragma unroll
        for (int i = 0; i < 2; i++)
#pragma unroll
            for (int j = 0; j < 2; j++)
                wmma::store_matrix_sync(&Sb[(wm * 32 + i * 16) * 72 + wn * 32 + j * 16],
                                        cf[i][j], 72, wmma::mem_row_major);
        __syncthreads();

#pragma unroll
        for (int i = 0; i < 32; i++) {
            int e = t + i * 256;
            int row = e >> 6;
            int q = q0 + row;
            float s = Sb[row * 72 + col];
            if (k <= q) part += __expf((s + (float)(k - q)) * SCALE);
        }
        __syncthreads();
    }

    __shared__ float red[256];
    red[t] = part;
    __syncthreads();
    if (t < 64) {
        float tot = red[t] + red[t + 64] + red[t + 128] + red[t + 192];
        g_den[(size_t)bh * SEQ + kt * 64 + t] = 1.0f / tot;
    }
}

// ---------------------------------------------------------------------------
// Pass B: O[q,:] = sum_k exp(y[q,k]) * invden[k] * V[k,:]  (flash-style)
// block = (qt: 128 q-rows, bh). Scores recomputed per 64-k tile.
// ---------------------------------------------------------------------------
__global__ __launch_bounds__(256) void attn_kernel() {
    int qt = gridDim.x - 1 - blockIdx.x;  // heavy blocks first
    int bh = blockIdx.y;
    int b = bh >> 4, h = bh & 15;

    extern __shared__ float sm[];
    float* Qs = sm;               // 128*72
    float* Ks = Qs + 128 * 72;    // 64*72
    float* Vs = Ks + 64 * 72;     // 64*72
    float* Ps = Vs + 64 * 72;     // 128*72

    int t = threadIdx.x, wid = t >> 5;
    int wm = wid >> 1, wn = wid & 1;

    const float* Qb = g_Q + ((size_t)bh * SEQ + (size_t)qt * 128) * DHEAD;
#pragma unroll
    for (int j = 0; j < 8; j++) {
        int id = t + j * 256;
        int row = id >> 4, c4 = (id & 15) << 2;
        *(float4*)&Qs[row * 72 + c4] = *(const float4*)&Qb[(size_t)row * DHEAD + c4];
    }

    FragC oacc[2][2];
#pragma unroll
    for (int i = 0; i < 2; i++)
#pragma unroll
        for (int j = 0; j < 2; j++) wmma::fill_fragment(oacc[i][j], 0.0f);

    int col = t & 63;
    int ktmax = 2 * qt + 1;

    for (int kt = 0; kt <= ktmax; kt++) {
        int k0 = kt * 64;
        const float* Kb = g_K + ((size_t)bh * SEQ + k0) * DHEAD;
        const float* Vb = g_V + ((size_t)bh * SEQ + k0) * DHEAD;
#pragma unroll
        for (int j = 0; j < 4; j++) {
            int id = t + j * 256;
            int row = id >> 4, c4 = (id & 15) << 2;
            *(float4*)&Ks[row * 72 + c4] = *(const float4*)&Kb[(size_t)row * DHEAD + c4];
            *(float4*)&Vs[row * 72 + c4] = *(const float4*)&Vb[(size_t)row * DHEAD + c4];
        }
        __syncthreads();

        FragC sf[2][2];
#pragma unroll
        for (int i = 0; i < 2; i++)
#pragma unroll
            for (int j = 0; j < 2; j++) wmma::fill_fragment(sf[i][j], 0.0f);

#pragma unroll
        for (int ks = 0; ks < 64; ks += 8) {
            FragA a[2];
            FragBt bf[2];
#pragma unroll
            for (int i = 0; i < 2; i++) {
                wmma::load_matrix_sync(a[i], &Qs[(wm * 32 + i * 16) * 72 + ks], 72);
                to_tf32(a[i]);
            }
#pragma unroll
            for (int j = 0; j < 2; j++) {
                wmma::load_matrix_sync(bf[j], &Ks[(wn * 32 + j * 16) * 72 + ks], 72);
                to_tf32(bf[j]);
            }
#pragma unroll
            for (int i = 0; i < 2; i++)
#pragma unroll
                for (int j = 0; j < 2; j++)
                    wmma::mma_sync(sf[i][j], a[i], bf[j], sf[i][j]);
        }
#pragma unroll
        for (int i = 0; i < 2; i++)
#pragma unroll
            for (int j = 0; j < 2; j++)
                wmma::store_matrix_sync(&Ps[(wm * 32 + i * 16) * 72 + wn * 32 + j * 16],
                                        sf[i][j], 72, wmma::mem_row_major);
        __syncthreads();

        float iv = g_den[(size_t)bh * SEQ + k0 + col];
        int k = k0 + col;
#pragma unroll
        for (int i = 0; i < 32; i++) {
            int e = t + i * 256;
            int row = e >> 6;
            int q = qt * 128 + row;
            float s = Ps[row * 72 + col];
            float v = (k <= q) ? __expf((s + (float)(k - q)) * SCALE) * iv : 0.0f;
            Ps[row * 72 + col] = v;
        }
        __syncthreads();

#pragma unroll
        for (int ks = 0; ks < 64; ks += 8) {
            FragA a[2];
            FragB bf[2];
#pragma unroll
            for (int i = 0; i < 2; i++) {
                wmma::load_matrix_sync(a[i], &Ps[(wm * 32 + i * 16) * 72 + ks], 72);
                to_tf32(a[i]);
            }
#pragma unroll
            for (int j = 0; j < 2; j++) {
                wmma::load_matrix_sync(bf[j], &Vs[ks * 72 + wn * 32 + j * 16], 72);
                to_tf32(bf[j]);
            }
#pragma unroll
            for (int i = 0; i < 2; i++)
#pragma unroll
                for (int j = 0; j < 2; j++)
                    wmma::mma_sync(oacc[i][j], a[i], bf[j], oacc[i][j]);
        }
        __syncthreads();
    }

    float* Ob = g_Ocat + ((size_t)b * SEQ + (size_t)qt * 128) * DMODEL + (size_t)h * DHEAD;
#pragma unroll
    for (int i = 0; i < 2; i++)
#pragma unroll
        for (int j = 0; j < 2; j++)
            wmma::store_matrix_sync(&Ob[(size_t)(wm * 32 + i * 16) * DMODEL + wn * 32 + j * 16],
                                    oacc[i][j], DMODEL, wmma::mem_row_major);
}

// ---------------------------------------------------------------------------
// Output projection: Out[4096,1024] = g_Ocat[4096,1024] @ WO[1024,1024]
// ---------------------------------------------------------------------------
__global__ __launch_bounds__(256) void out_kernel(const float* __restrict__ WO,
                                                  float* __restrict__ Out) {
    int mt = blockIdx.x;  // 0..31 (128 rows)
    int nt = blockIdx.y;  // 0..15 (64 cols)

    __shared__ alignas(16) float Xs[128][40];
    __shared__ alignas(16) float Ws[32][72];

    int t = threadIdx.x, wid = t >> 5;
    int wm = wid >> 1, wn = wid & 1;

    FragC c[2][2];
#pragma unroll
    for (int i = 0; i < 2; i++)
#pragma unroll
        for (int j = 0; j < 2; j++) wmma::fill_fragment(c[i][j], 0.0f);

    const float* Xb = g_Ocat + (size_t)mt * 128 * DMODEL;
    const float* Wb = WO + (size_t)nt * 64;

    for (int kk = 0; kk < DMODEL; kk += 32) {
#pragma unroll
        for (int j = 0; j < 4; j++) {
            int id = t + j * 256;
            int row = id >> 3, col = (id & 7) << 2;
            *(float4*)&Xs[row][col] = *(const float4*)&Xb[(size_t)row * DMODEL + kk + col];
        }
#pragma unroll
        for (int j = 0; j < 2; j++) {
            int id = t + j * 256;
            int row = id >> 4, col = (id & 15) << 2;
            *(float4*)&Ws[row][col] = *(const float4*)&Wb[(size_t)(kk + row) * DMODEL + col];
        }
        __syncthreads();
#pragma unroll
        for (int ks = 0; ks < 32; ks += 8) {
            FragA a[2];
            FragB bf[2];
#pragma unroll
            for (int i = 0; i < 2; i++) {
                wmma::load_matrix_sync(a[i], &Xs[wm * 32 + i * 16][ks], 40);
                to_tf32(a[i]);
            }
#pragma unroll
            for (int j = 0; j < 2; j++) {
                wmma::load_matrix_sync(bf[j], &Ws[ks][wn * 32 + j * 16], 72);
                to_tf32(bf[j]);
            }
#pragma unroll
            for (int i = 0; i < 2; i++)
#pragma unroll
                for (int j = 0; j < 2; j++)
                    wmma::mma_sync(c[i][j], a[i], bf[j], c[i][j]);
        }
        __syncthreads();
    }

    float* Ob = Out + (size_t)mt * 128 * DMODEL + (size_t)nt * 64;
#pragma unroll
    for (int i = 0; i < 2; i++)
#pragma unroll
        for (int j = 0; j < 2; j++)
            wmma::store_matrix_sync(&Ob[(size_t)(wm * 32 + i * 16) * DMODEL + wn * 32 + j * 16],
                                    c[i][j], DMODEL, wmma::mem_row_major);
}

// ---------------------------------------------------------------------------
// Launch. Inputs: keys, queries, values, WQ, WK, WV, WO, masking
// ---------------------------------------------------------------------------
extern "C" void kernel_launch(void* const* d_in, const int* in_sizes, int n_in,
                              void* d_out, int out_size) {
    const float* keys    = (const float*)d_in[0];
    const float* queries = (const float*)d_in[1];
    const float* values  = (const float*)d_in[2];
    const float* WQ      = (const float*)d_in[3];
    const float* WK      = (const float*)d_in[4];
    const float* WV      = (const float*)d_in[5];
    const float* WO      = (const float*)d_in[6];
    float* out = (float*)d_out;
    (void)in_sizes; (void)n_in; (void)out_size;

    static const size_t denSmem  = (size_t)(128 * 72 + 64 * 72 + 128 * 72) * 4;           // 92160
    static const size_t attnSmem = (size_t)(128 * 72 + 64 * 72 + 64 * 72 + 128 * 72) * 4; // 110592
    cudaFuncSetAttribute(den_kernel,  cudaFuncAttributeMaxDynamicSharedMemorySize, (int)denSmem);
    cudaFuncSetAttribute(attn_kernel, cudaFuncAttributeMaxDynamicSharedMemorySize, (int)attnSmem);

    proj_kernel<<<dim3(SEQ / 128, NHEAD, 6), 256>>>(queries, keys, values, WQ, WK, WV);
    den_kernel<<<dim3(SEQ / 64, BH), 256, denSmem>>>();
    attn_kernel<<<dim3(SEQ / 128, BH), 256, attnSmem>>>();
    out_kernel<<<dim3((BATCH * SEQ) / 128, DMODEL / 64), 256>>>(WO, out);
}

// round 3
// speedup vs baseline: 1.5037x; 1.4148x over previous
#include <cuda_runtime.h>
#include <mma.h>
#include <cstdint>
#include <cstddef>

using namespace nvcuda;

#define BATCH  2
#define SEQ    2048
#define DMODEL 1024
#define NHEAD  16
#define DHEAD  64
#define BH     (BATCH*NHEAD)

// Scratch (device globals: allocation-free rule). All values stored PRE-ROUNDED to tf32.
__device__ __align__(16) float g_Q[(size_t)BH * SEQ * DHEAD];        // 16 MB
__device__ __align__(16) float g_K[(size_t)BH * SEQ * DHEAD];        // 16 MB
__device__ __align__(16) float g_V[(size_t)BH * SEQ * DHEAD];        // 16 MB (scaled in-place by 1/den)
__device__ __align__(16) float g_P[(size_t)BH * SEQ * SEQ];          // 512 MB, causal part written
__device__ __align__(16) float g_den[(size_t)BH * SEQ];              // 1/colsum
__device__ __align__(16) float g_Ocat[(size_t)BATCH * SEQ * DMODEL]; // 16 MB

typedef wmma::fragment<wmma::matrix_a, 16, 16, 8, wmma::precision::tf32, wmma::row_major> FragA;
typedef wmma::fragment<wmma::matrix_b, 16, 16, 8, wmma::precision::tf32, wmma::row_major> FragB;
typedef wmma::fragment<wmma::matrix_b, 16, 16, 8, wmma::precision::tf32, wmma::col_major> FragBt;
typedef wmma::fragment<wmma::accumulator, 16, 16, 8, float> FragC;

__device__ __forceinline__ float rtf(float x) { return wmma::__float_to_tf32(x); }
__device__ __forceinline__ float4 rtf4(float4 v) {
    v.x = rtf(v.x); v.y = rtf(v.y); v.z = rtf(v.z); v.w = rtf(v.w);
    return v;
}

#define SCALE 0.022097086912079608f  // 1/sqrt(2048)

// ---------------------------------------------------------------------------
// Fused per-head projections: {Q,K,V}[bh, s, e] = X[b, s, :] @ W[h, :, e]
// Inputs rounded to tf32 at smem store; outputs rounded to tf32 at epilogue.
// blockIdx: x = 128-row tile (16), y = head (16), z = which*2 + b (6)
// ---------------------------------------------------------------------------
__global__ __launch_bounds__(256) void proj_kernel(
    const float* __restrict__ Xq, const float* __restrict__ Xk, const float* __restrict__ Xv,
    const float* __restrict__ WQ, const float* __restrict__ WK, const float* __restrict__ WV) {
    int mt = blockIdx.x, h = blockIdx.y, z = blockIdx.z;
    int which = z >> 1, b = z & 1;
    const float* X = (which == 0) ? Xq : (which == 1) ? Xk : Xv;
    const float* W = (which == 0) ? WQ : (which == 1) ? WK : WV;
    float* Outp    = (which == 0) ? g_Q : (which == 1) ? g_K : g_V;

    __shared__ alignas(16) float Xs[128][40];  // 128x32, pad 8
    __shared__ alignas(16) float Ws[32][72];   // 32x64, pad 8

    int t = threadIdx.x, wid = t >> 5;
    int wm = wid >> 1, wn = wid & 1;  // 4x2 warps -> 128x64

    FragC c[2][2];
#pragma unroll
    for (int i = 0; i < 2; i++)
#pragma unroll
        for (int j = 0; j < 2; j++) wmma::fill_fragment(c[i][j], 0.0f);

    const float* Xb = X + (size_t)b * SEQ * DMODEL + (size_t)mt * 128 * DMODEL;
    const float* Wh = W + (size_t)h * DMODEL * DHEAD;

    for (int kk = 0; kk < DMODEL; kk += 32) {
#pragma unroll
        for (int j = 0; j < 4; j++) {
            int id = t + j * 256;
            int row = id >> 3, col = (id & 7) << 2;
            *(float4*)&Xs[row][col] = rtf4(*(const float4*)&Xb[(size_t)row * DMODEL + kk + col]);
        }
#pragma unroll
        for (int j = 0; j < 2; j++) {
            int id = t + j * 256;
            int row = id >> 4, col = (id & 15) << 2;
            *(float4*)&Ws[row][col] = rtf4(*(const float4*)&Wh[(size_t)(kk + row) * DHEAD + col]);
        }
        __syncthreads();
#pragma unroll
        for (int ks = 0; ks < 32; ks += 8) {
            FragA a[2];
            FragB bf[2];
#pragma unroll
            for (int i = 0; i < 2; i++)
                wmma::load_matrix_sync(a[i], &Xs[wm * 32 + i * 16][ks], 40);
#pragma unroll
            for (int j = 0; j < 2; j++)
                wmma::load_matrix_sync(bf[j], &Ws[ks][wn * 32 + j * 16], 72);
#pragma unroll
            for (int i = 0; i < 2; i++)
#pragma unroll
                for (int j = 0; j < 2; j++)
                    wmma::mma_sync(c[i][j], a[i], bf[j], c[i][j]);
        }
        __syncthreads();
    }

    float* Ob = Outp + ((size_t)(b * NHEAD + h) * SEQ + (size_t)mt * 128) * DHEAD;
#pragma unroll
    for (int i = 0; i < 2; i++)
#pragma unroll
        for (int j = 0; j < 2; j++) {
#pragma unroll
            for (int e = 0; e < c[i][j].num_elements; e++) c[i][j].x[e] = rtf(c[i][j].x[e]);
            wmma::store_matrix_sync(&Ob[(size_t)(wm * 32 + i * 16) * DHEAD + wn * 32 + j * 16],
                                    c[i][j], DHEAD, wmma::mem_row_major);
        }
}

// ---------------------------------------------------------------------------
// den_kernel: per (64-col k-stripe, bh):
//   - scores S = Q K^T via wmma over all q-tiles >= stripe
//   - P = exp((S + (k-q))*SCALE) causal, written to g_P (tf32-rounded)
//   - column sums -> g_den = 1/sum
// Score buffer overlays the Q tile (reloaded every iteration anyway).
// ---------------------------------------------------------------------------
__global__ __launch_bounds__(256) void den_kernel() {
    int kt = gridDim.x - 1 - blockIdx.x;  // long-running stripes first
    int bh = blockIdx.y;

    extern __shared__ float sm[];
    float* Qs = sm;              // 128*72 (also score buffer)
    float* Ks = Qs + 128 * 72;   // 64*72

    int t = threadIdx.x, wid = t >> 5;
    int wm = wid >> 1, wn = wid & 1;

    const float* Qb = g_Q + (size_t)bh * SEQ * DHEAD;
    const float* Kb = g_K + ((size_t)bh * SEQ + (size_t)kt * 64) * DHEAD;
    float* Pb = g_P + (size_t)bh * SEQ * SEQ + (size_t)kt * 64;

#pragma unroll
    for (int j = 0; j < 4; j++) {
        int id = t + j * 256;
        int row = id >> 4, col = (id & 15) << 2;
        *(float4*)&Ks[row * 72 + col] = *(const float4*)&Kb[(size_t)row * DHEAD + col];
    }

    int col = t & 63;
    int ro  = t >> 6;         // 0..3
    int k   = kt * 64 + col;
    float part = 0.0f;

    for (int qt = kt >> 1; qt < SEQ / 128; qt++) {
        int q0 = qt * 128;
#pragma unroll
        for (int j = 0; j < 8; j++) {
            int id = t + j * 256;
            int row = id >> 4, c4 = (id & 15) << 2;
            *(float4*)&Qs[row * 72 + c4] = *(const float4*)&Qb[(size_t)(q0 + row) * DHEAD + c4];
        }
        __syncthreads();

        FragC cf[2][2];
#pragma unroll
        for (int i = 0; i < 2; i++)
#pragma unroll
            for (int j = 0; j < 2; j++) wmma::fill_fragment(cf[i][j], 0.0f);

#pragma unroll
        for (int ks = 0; ks < 64; ks += 8) {
            FragA a[2];
            FragBt bf[2];
#pragma unroll
            for (int i = 0; i < 2; i++)
                wmma::load_matrix_sync(a[i], &Qs[(wm * 32 + i * 16) * 72 + ks], 72);
#pragma unroll
            for (int j = 0; j < 2; j++)
                wmma::load_matrix_sync(bf[j], &Ks[(wn * 32 + j * 16) * 72 + ks], 72);
#pragma unroll
            for (int i = 0; i < 2; i++)
#pragma unroll
                for (int j = 0; j < 2; j++)
                    wmma::mma_sync(cf[i][j], a[i], bf[j], cf[i][j]);
        }
        __syncthreads();  // all warps done reading Qs -> safe to overlay scores
#pragma unroll
        for (int i = 0; i < 2; i++)
#pragma unroll
            for (int j = 0; j < 2; j++)
                wmma::store_matrix_sync(&Qs[(wm * 32 + i * 16) * 72 + wn * 32 + j * 16],
                                        cf[i][j], 72, wmma::mem_row_major);
        __syncthreads();

#pragma unroll
        for (int i = 0; i < 32; i++) {
            int row = ro + i * 4;
            int q = q0 + row;
            float s = Qs[row * 72 + col];
            float v = 0.0f;
            if (k <= q) v = __expf((s + (float)(k - q)) * SCALE);
            part += v;
            Pb[(size_t)q * SEQ + col] = rtf(v);
        }
        __syncthreads();
    }

    __shared__ float red[256];
    red[t] = part;
    __syncthreads();
    if (t < 64) {
        float tot = red[t] + red[t + 64] + red[t + 128] + red[t + 192];
        g_den[(size_t)bh * SEQ + kt * 64 + t] = 1.0f / tot;
    }
}

// ---------------------------------------------------------------------------
// vscale_kernel: g_V[bh,k,e] *= g_den[bh,k]  (in place; proj rewrites V each replay)
// ---------------------------------------------------------------------------
__global__ __launch_bounds__(256) void vscale_kernel() {
    int idx = blockIdx.x * 256 + threadIdx.x;     // float4 index
    int e4 = idx & 15;
    int k  = (idx >> 4) & (SEQ - 1);
    int bh = idx >> 15;
    float iv = g_den[(size_t)bh * SEQ + k];
    float4* p = (float4*)&g_V[((size_t)bh * SEQ + k) * DHEAD + e4 * 4];
    float4 v = *p;
    v.x = rtf(v.x * iv); v.y = rtf(v.y * iv); v.z = rtf(v.z * iv); v.w = rtf(v.w * iv);
    *p = v;
}

// ---------------------------------------------------------------------------
// pv_kernel: Ocat[b, q, h*64+e] = sum_k P[q,k] * V'[k,e]   (V' pre-scaled)
// All operands pre-rounded tf32 -> pure load+mma inner loop.
// ---------------------------------------------------------------------------
__global__ __launch_bounds__(256) void pv_kernel() {
    int qt = gridDim.x - 1 - blockIdx.x;  // heavy blocks first
    int bh = blockIdx.y;
    int b = bh >> 4, h = bh & 15;

    extern __shared__ float sm[];
    float* Ps = sm;               // 128*72
    float* Vs = Ps + 128 * 72;    // 64*72

    int t = threadIdx.x, wid = t >> 5;
    int wm = wid >> 1, wn = wid & 1;

    FragC oacc[2][2];
#pragma unroll
    for (int i = 0; i < 2; i++)
#pragma unroll
        for (int j = 0; j < 2; j++) wmma::fill_fragment(oacc[i][j], 0.0f);

    const float* Prow = g_P + ((size_t)bh * SEQ + (size_t)qt * 128) * SEQ;
    const float* Vb = g_V + (size_t)bh * SEQ * DHEAD;
    int ktmax = 2 * qt + 1;

    for (int kt = 0; kt <= ktmax; kt++) {
        int k0 = kt * 64;
#pragma unroll
        for (int j = 0; j < 8; j++) {
            int id = t + j * 256;
            int row = id >> 4, c4 = (id & 15) << 2;
            *(float4*)&Ps[row * 72 + c4] =
                *(const float4*)&Prow[(size_t)row * SEQ + k0 + c4];
        }
#pragma unroll
        for (int j = 0; j < 4; j++) {
            int id = t + j * 256;
            int row = id >> 4, c4 = (id & 15) << 2;
            *(float4*)&Vs[row * 72 + c4] = *(const float4*)&Vb[(size_t)(k0 + row) * DHEAD + c4];
        }
        __syncthreads();

#pragma unroll
        for (int ks = 0; ks < 64; ks += 8) {
            FragA a[2];
            FragB bf[2];
#pragma unroll
            for (int i = 0; i < 2; i++)
                wmma::load_matrix_sync(a[i], &Ps[(wm * 32 + i * 16) * 72 + ks], 72);
#pragma unroll
            for (int j = 0; j < 2; j++)
                wmma::load_matrix_sync(bf[j], &Vs[ks * 72 + wn * 32 + j * 16], 72);
#pragma unroll
            for (int i = 0; i < 2; i++)
#pragma unroll
                for (int j = 0; j < 2; j++)
                    wmma::mma_sync(oacc[i][j], a[i], bf[j], oacc[i][j]);
        }
        __syncthreads();
    }

    float* Ob = g_Ocat + ((size_t)b * SEQ + (size_t)qt * 128) * DMODEL + (size_t)h * DHEAD;
#pragma unroll
    for (int i = 0; i < 2; i++)
#pragma unroll
        for (int j = 0; j < 2; j++) {
#pragma unroll
            for (int e = 0; e < oacc[i][j].num_elements; e++) oacc[i][j].x[e] = rtf(oacc[i][j].x[e]);
            wmma::store_matrix_sync(&Ob[(size_t)(wm * 32 + i * 16) * DMODEL + wn * 32 + j * 16],
                                    oacc[i][j], DMODEL, wmma::mem_row_major);
        }
}

// ---------------------------------------------------------------------------
// Output projection: Out[4096,1024] = g_Ocat @ WO. Ocat pre-rounded; WO rounded
// at smem store.
// ---------------------------------------------------------------------------
__global__ __launch_bounds__(256) void out_kernel(const float* __restrict__ WO,
                                                  float* __restrict__ Out) {
    int mt = blockIdx.x;  // 0..31 (128 rows)
    int nt = blockIdx.y;  // 0..15 (64 cols)

    __shared__ alignas(16) float Xs[128][40];
    __shared__ alignas(16) float Ws[32][72];

    int t = threadIdx.x, wid = t >> 5;
    int wm = wid >> 1, wn = wid & 1;

    FragC c[2][2];
#pragma unroll
    for (int i = 0; i < 2; i++)
#pragma unroll
        for (int j = 0; j < 2; j++) wmma::fill_fragment(c[i][j], 0.0f);

    const float* Xb = g_Ocat + (size_t)mt * 128 * DMODEL;
    const float* Wb = WO + (size_t)nt * 64;

    for (int kk = 0; kk < DMODEL; kk += 32) {
#pragma unroll
        for (int j = 0; j < 4; j++) {
            int id = t + j * 256;
            int row = id >> 3, col = (id & 7) << 2;
            *(float4*)&Xs[row][col] = *(const float4*)&Xb[(size_t)row * DMODEL + kk + col];
        }
#pragma unroll
        for (int j = 0; j < 2; j++) {
            int id = t + j * 256;
            int row = id >> 4, col = (id & 15) << 2;
            *(float4*)&Ws[row][col] = rtf4(*(const float4*)&Wb[(size_t)(kk + row) * DMODEL + col]);
        }
        __syncthreads();
#pragma unroll
        for (int ks = 0; ks < 32; ks += 8) {
            FragA a[2];
            FragB bf[2];
#pragma unroll
            for (int i = 0; i < 2; i++)
                wmma::load_matrix_sync(a[i], &Xs[wm * 32 + i * 16][ks], 40);
#pragma unroll
            for (int j = 0; j < 2; j++)
                wmma::load_matrix_sync(bf[j], &Ws[ks][wn * 32 + j * 16], 72);
#pragma unroll
            for (int i = 0; i < 2; i++)
#pragma unroll
                for (int j = 0; j < 2; j++)
                    wmma::mma_sync(c[i][j], a[i], bf[j], c[i][j]);
        }
        __syncthreads();
    }

    float* Ob = Out + (size_t)mt * 128 * DMODEL + (size_t)nt * 64;
#pragma unroll
    for (int i = 0; i < 2; i++)
#pragma unroll
        for (int j = 0; j < 2; j++)
            wmma::store_matrix_sync(&Ob[(size_t)(wm * 32 + i * 16) * DMODEL + wn * 32 + j * 16],
                                    c[i][j], DMODEL, wmma::mem_row_major);
}

// ---------------------------------------------------------------------------
// Launch. Inputs: keys, queries, values, WQ, WK, WV, WO, masking
// ---------------------------------------------------------------------------
extern "C" void kernel_launch(void* const* d_in, const int* in_sizes, int n_in,
                              void* d_out, int out_size) {
    const float* keys    = (const float*)d_in[0];
    const float* queries = (const float*)d_in[1];
    const float* values  = (const float*)d_in[2];
    const float* WQ      = (const float*)d_in[3];
    const float* WK      = (const float*)d_in[4];
    const float* WV      = (const float*)d_in[5];
    const float* WO      = (const float*)d_in[6];
    float* out = (float*)d_out;
    (void)in_sizes; (void)n_in; (void)out_size;

    static const size_t denSmem = (size_t)(128 * 72 + 64 * 72) * 4;  // 55296
    static const size_t pvSmem  = (size_t)(128 * 72 + 64 * 72) * 4;  // 55296
    cudaFuncSetAttribute(den_kernel, cudaFuncAttributeMaxDynamicSharedMemorySize, (int)denSmem);
    cudaFuncSetAttribute(pv_kernel,  cudaFuncAttributeMaxDynamicSharedMemorySize, (int)pvSmem);

    proj_kernel<<<dim3(SEQ / 128, NHEAD, 6), 256>>>(queries, keys, values, WQ, WK, WV);
    den_kernel<<<dim3(SEQ / 64, BH), 256, denSmem>>>();
    vscale_kernel<<<(BH * SEQ * DHEAD / 4) / 256, 256>>>();
    pv_kernel<<<dim3(SEQ / 128, BH), 256, pvSmem>>>();
    out_kernel<<<dim3((BATCH * SEQ) / 128, DMODEL / 64), 256>>>(WO, out);
}